// round 13
// baseline (speedup 1.0000x reference)
#include <cuda_runtime.h>
#include <cuda_bf16.h>

// Sparsity_60095182405891: x[64,256,56,56] f32, NCHW.
// mask1: keep top-2 (ties >=) of |x| per 4-channel block.
// mask2: zero kept, keep top-1 (ties >=) of residual per 8-channel block.
// out = x * (mask1 | mask2).
//
// R13 = R12 (LDG.256/STG.256 win: 55.65us, 80.6% DRAM, best of session)
// + .cs streaming qualifier on the v8 ld/st (one-pass data, evict-first;
// was neutral at 128-bit, free to carry here).
// Decomposition: one thread per (4-channel block, 8-float chunk):
// 4x LDG.256 + 4x STG.256, 32 value regs (regs=47, no spills, occ 54%),
// 8-block residual max via shfl_xor(1) to the partner thread (adjacent
// tid, same warp, other 4 channels at the same pixels).
// History: 128-bit configs plateaued at 6.22-6.34 TB/s; 256-bit requests
// trimmed L1tex/LSU wavefront overhead -> 6.38 TB/s.

#define C_TOT   256
#define HW      3136             // 56*56
#define CHUNKS  (HW / 8)         // 392 8-float chunks per plane
#define GROUPS  (C_TOT / 8)      // 32
#define TILES_PER_IMG (GROUPS * CHUNKS * 2)   // 25088 = 98 * 256

__device__ __forceinline__ void ldg256_cs(const float* p, float* v) {
    asm volatile("ld.global.cs.v8.f32 {%0,%1,%2,%3,%4,%5,%6,%7}, [%8];"
        : "=f"(v[0]), "=f"(v[1]), "=f"(v[2]), "=f"(v[3]),
          "=f"(v[4]), "=f"(v[5]), "=f"(v[6]), "=f"(v[7])
        : "l"(p));
}

__device__ __forceinline__ void stg256_cs(float* p, const float* v) {
    asm volatile("st.global.cs.v8.f32 [%0], {%1,%2,%3,%4,%5,%6,%7,%8};"
        :: "l"(p),
           "f"(v[0]), "f"(v[1]), "f"(v[2]), "f"(v[3]),
           "f"(v[4]), "f"(v[5]), "f"(v[6]), "f"(v[7])
        : "memory");
}

__device__ __forceinline__ float second_of_4(float a0, float a1, float a2, float a3) {
    float m01 = fmaxf(a0, a1), n01 = fminf(a0, a1);
    float m23 = fmaxf(a2, a3), n23 = fminf(a2, a3);
    return fmaxf(fminf(m01, m23), fmaxf(n01, n23));
}

__global__ void __launch_bounds__(256)
sparsity_nm_kernel(const float* __restrict__ x, float* __restrict__ out) {
    int tid = blockIdx.x * 256 + threadIdx.x;   // 0 .. 25087 (exact)
    int n   = blockIdx.y;

    int half    = tid & 1;          // which 4-channel half of the 8-block
    int pairIdx = tid >> 1;         // 0 .. 12543
    int g8      = pairIdx / CHUNKS; // 8-channel group (0..31)
    int chunk   = pairIdx - g8 * CHUNKS;  // 8-float chunk in plane (0..391)

    int c0 = g8 * 8 + half * 4;
    long base = ((long)(n * C_TOT + c0)) * HW + (long)chunk * 8;

    const float* xin = x + base;
    float*       xo  = out + base;

    // 4 independent 256-bit streaming loads (channel stride 12544 B, 32B aligned)
    float val[4][8];
#pragma unroll
    for (int c = 0; c < 4; c++) {
        ldg256_cs(xin + (long)c * HW, val[c]);
    }

#pragma unroll
    for (int l = 0; l < 8; l++) {
        float a[4];
#pragma unroll
        for (int c = 0; c < 4; c++) a[c] = fabsf(val[c][l]);

        // mask1: top-2 (ties kept) within this 4-channel block
        float thr = second_of_4(a[0], a[1], a[2], a[3]);

        bool  m1[4];
        float r[4];
        float rmax = 0.0f;
#pragma unroll
        for (int c = 0; c < 4; c++) {
            m1[c] = (a[c] >= thr);
            r[c]  = m1[c] ? 0.0f : a[c];
            rmax  = fmaxf(rmax, r[c]);
        }

        // 8-block residual max: partner thread (adjacent tid, same warp)
        // holds the other 4 channels at the same pixels.
        rmax = fmaxf(rmax, __shfl_xor_sync(0xffffffffu, rmax, 1));

        // mask2: top-1 (ties kept) of residual over the 8-block; OR mask1
#pragma unroll
        for (int c = 0; c < 4; c++) {
            bool keep = m1[c] || (r[c] >= rmax);
            val[c][l] = keep ? val[c][l] : 0.0f;
        }
    }

    // 4 independent 256-bit streaming stores
#pragma unroll
    for (int c = 0; c < 4; c++) {
        stg256_cs(xo + (long)c * HW, val[c]);
    }
}

extern "C" void kernel_launch(void* const* d_in, const int* in_sizes, int n_in,
                              void* d_out, int out_size) {
    const float* x = (const float*)d_in[0];
    float* out = (float*)d_out;
    dim3 grid(TILES_PER_IMG / 256, 64);   // (98, 64)
    sparsity_nm_kernel<<<grid, 256>>>(x, out);
}

// round 14
// speedup vs baseline: 1.0045x; 1.0045x over previous
#include <cuda_runtime.h>
#include <cuda_bf16.h>

// Sparsity_60095182405891: x[64,256,56,56] f32, NCHW.
// mask1: keep top-2 (ties >=) of |x| per 4-channel block.
// mask2: zero kept, keep top-1 (ties >=) of residual per 8-channel block.
// out = x * (mask1 | mask2).
//
// R14 = R12 exactly (plain LDG.256/STG.256, no cache-op qualifier).
// R12 measured 55.65us / 80.6% DRAM (best of session); R13's .cs variant
// measured 56.32/79.6 (no upside -> qualifier dropped). This run is the
// A/A replication of R12.
// Decomposition: one thread per (4-channel block, 8-float chunk):
// 4x LDG.256 + 4x STG.256, 32 value regs (regs=47, no spills, occ ~54%),
// 8-block residual max via shfl_xor(1) to the partner thread (adjacent
// tid, same warp, other 4 channels at the same pixels).
// History: all 128-bit configs plateaued at 6.22-6.34 TB/s; 256-bit
// requests (half the L1tex/LSU wavefronts, 32B/lane span) -> 6.38 TB/s.

#define C_TOT   256
#define HW      3136             // 56*56
#define CHUNKS  (HW / 8)         // 392 8-float chunks per plane
#define GROUPS  (C_TOT / 8)      // 32
#define TILES_PER_IMG (GROUPS * CHUNKS * 2)   // 25088 = 98 * 256

__device__ __forceinline__ void ldg256(const float* p, float* v) {
    asm volatile("ld.global.v8.f32 {%0,%1,%2,%3,%4,%5,%6,%7}, [%8];"
        : "=f"(v[0]), "=f"(v[1]), "=f"(v[2]), "=f"(v[3]),
          "=f"(v[4]), "=f"(v[5]), "=f"(v[6]), "=f"(v[7])
        : "l"(p));
}

__device__ __forceinline__ void stg256(float* p, const float* v) {
    asm volatile("st.global.v8.f32 [%0], {%1,%2,%3,%4,%5,%6,%7,%8};"
        :: "l"(p),
           "f"(v[0]), "f"(v[1]), "f"(v[2]), "f"(v[3]),
           "f"(v[4]), "f"(v[5]), "f"(v[6]), "f"(v[7])
        : "memory");
}

__device__ __forceinline__ float second_of_4(float a0, float a1, float a2, float a3) {
    float m01 = fmaxf(a0, a1), n01 = fminf(a0, a1);
    float m23 = fmaxf(a2, a3), n23 = fminf(a2, a3);
    return fmaxf(fminf(m01, m23), fmaxf(n01, n23));
}

__global__ void __launch_bounds__(256)
sparsity_nm_kernel(const float* __restrict__ x, float* __restrict__ out) {
    int tid = blockIdx.x * 256 + threadIdx.x;   // 0 .. 25087 (exact)
    int n   = blockIdx.y;

    int half    = tid & 1;          // which 4-channel half of the 8-block
    int pairIdx = tid >> 1;         // 0 .. 12543
    int g8      = pairIdx / CHUNKS; // 8-channel group (0..31)
    int chunk   = pairIdx - g8 * CHUNKS;  // 8-float chunk in plane (0..391)

    int c0 = g8 * 8 + half * 4;
    long base = ((long)(n * C_TOT + c0)) * HW + (long)chunk * 8;

    const float* xin = x + base;
    float*       xo  = out + base;

    // 4 independent 256-bit loads (channel stride 12544 B; 32B aligned)
    float val[4][8];
#pragma unroll
    for (int c = 0; c < 4; c++) {
        ldg256(xin + (long)c * HW, val[c]);
    }

#pragma unroll
    for (int l = 0; l < 8; l++) {
        float a[4];
#pragma unroll
        for (int c = 0; c < 4; c++) a[c] = fabsf(val[c][l]);

        // mask1: top-2 (ties kept) within this 4-channel block
        float thr = second_of_4(a[0], a[1], a[2], a[3]);

        bool  m1[4];
        float r[4];
        float rmax = 0.0f;
#pragma unroll
        for (int c = 0; c < 4; c++) {
            m1[c] = (a[c] >= thr);
            r[c]  = m1[c] ? 0.0f : a[c];
            rmax  = fmaxf(rmax, r[c]);
        }

        // 8-block residual max: partner thread (adjacent tid, same warp)
        // holds the other 4 channels at the same pixels.
        rmax = fmaxf(rmax, __shfl_xor_sync(0xffffffffu, rmax, 1));

        // mask2: top-1 (ties kept) of residual over the 8-block; OR mask1
#pragma unroll
        for (int c = 0; c < 4; c++) {
            bool keep = m1[c] || (r[c] >= rmax);
            val[c][l] = keep ? val[c][l] : 0.0f;
        }
    }

    // 4 independent 256-bit stores
#pragma unroll
    for (int c = 0; c < 4; c++) {
        stg256(xo + (long)c * HW, val[c]);
    }
}

extern "C" void kernel_launch(void* const* d_in, const int* in_sizes, int n_in,
                              void* d_out, int out_size) {
    const float* x = (const float*)d_in[0];
    float* out = (float*)d_out;
    dim3 grid(TILES_PER_IMG / 256, 64);   // (98, 64)
    sparsity_nm_kernel<<<grid, 256>>>(x, out);
}